// round 4
// baseline (speedup 1.0000x reference)
#include <cuda_runtime.h>
#include <math_constants.h>
#include <stdint.h>

#define C_CLASSES 1000
#define NB 15
#define NSEG (C_CLASSES * NB)
#define NF4 250            // float4 chunks per row
#define JMAX 8             // ceil(NF4/32)
#define GRID 296
#define TPB 256

// Scratch accumulators. Zero at module load; the last-finishing block restores
// everything it consumed to zero, so each launch / graph replay starts clean.
__device__ float g_colsum[C_CLASSES];   // per-class sum of probs (all bins)
__device__ float g_cnthi[NSEG];         // counts for bins >= 1 (bin0 implicit)
__device__ float g_confhi[NSEG];        // conf sums for bins >= 1
__device__ float g_acc[NSEG];           // label-match counts, all bins
__device__ unsigned g_ticket;           // block-completion ticket (self-wrapping)
__device__ int g_rareflag;              // any row had s < NB (some p may exceed 1/NB)

__device__ __forceinline__ float ex2(float x) {
    float y;
    asm("ex2.approx.ftz.f32 %0, %1;" : "=f"(y) : "f"(x));
    return y;
}

__global__ __launch_bounds__(TPB, 2)
void ece_main_kernel(const float* __restrict__ logits,
                     const int*   __restrict__ labels,
                     int n, float* __restrict__ out) {
    const int lane = threadIdx.x & 31;
    const int gw   = blockIdx.x * (TPB >> 5) + (threadIdx.x >> 5); // global warp id
    const int W    = GRID * (TPB >> 5);                            // total warps

    __shared__ float shc[C_CLASSES];
    for (int i = threadIdx.x; i < C_CLASSES; i += TPB) shc[i] = 0.0f;
    __syncthreads();

    // Per-thread column-sum accumulators: class 4*(j*32+lane)+k -> acc[j*4+k]
    float acc[32];
    #pragma unroll
    for (int i = 0; i < 32; i++) acc[i] = 0.0f;

    const float L2E = 1.4426950408889634f;
    const float NEG = -CUDART_INF_F;

    int r = gw;

    // ---- prologue: load first row ----
    float4 v[JMAX];
    int lab = 0;
    if (r < n) {
        const float* row = logits + (size_t)r * C_CLASSES;
        #pragma unroll
        for (int j = 0; j < JMAX; j++) {
            int idx = j * 32 + lane;
            v[j] = (idx < NF4) ? *(const float4*)(row + idx * 4)
                               : make_float4(NEG, NEG, NEG, NEG);
        }
        lab = __ldg(labels + r);
    }

    while (r < n) {
        const int rn = r + W;

        // ---- prefetch next row: overlaps this row's entire compute chain ----
        float4 nv[JMAX];
        int nlab = 0;
        if (rn < n) {
            const float* nrow = logits + (size_t)rn * C_CLASSES;
            #pragma unroll
            for (int j = 0; j < JMAX; j++) {
                int idx = j * 32 + lane;
                nv[j] = (idx < NF4) ? *(const float4*)(nrow + idx * 4)
                                    : make_float4(NEG, NEG, NEG, NEG);
            }
            nlab = __ldg(labels + rn);
        }

        // ---- row max: local tree + warp butterfly ----
        float m = NEG;
        #pragma unroll
        for (int j = 0; j < JMAX; j++) {
            float a = fmaxf(v[j].x, v[j].y);
            float b = fmaxf(v[j].z, v[j].w);
            m = fmaxf(m, fmaxf(a, b));
        }
        #pragma unroll
        for (int o = 16; o; o >>= 1)
            m = fmaxf(m, __shfl_xor_sync(0xFFFFFFFFu, m, o));

        // ---- exp via single MUFU per element: e = 2^(x*L2E - m*L2E) ----
        const float m2 = m * L2E;
        float e[32];
        #pragma unroll
        for (int j = 0; j < JMAX; j++) {
            e[j * 4 + 0] = ex2(fmaf(v[j].x, L2E, -m2));
            e[j * 4 + 1] = ex2(fmaf(v[j].y, L2E, -m2));
            e[j * 4 + 2] = ex2(fmaf(v[j].z, L2E, -m2));
            e[j * 4 + 3] = ex2(fmaf(v[j].w, L2E, -m2));
        }

        // ---- row sum: local tree + warp butterfly ----
        float s = 0.0f;
        #pragma unroll
        for (int j = 0; j < JMAX; j++)
            s += (e[j * 4 + 0] + e[j * 4 + 1]) + (e[j * 4 + 2] + e[j * 4 + 3]);
        #pragma unroll
        for (int o = 16; o; o >>= 1)
            s += __shfl_xor_sync(0xFFFFFFFFu, s, o);

        const float inv = __fdividef(1.0f, s);

        // ---- accumulate per-class prob sums in registers (32 FFMA) ----
        #pragma unroll
        for (int i = 0; i < 32; i++)
            acc[i] = fmaf(e[i], inv, acc[i]);

        // ---- label bin: one atomic per row, handled by the owning lane ----
        if (((lab >> 2) & 31) == lane) {
            float xl = __ldg(logits + (size_t)r * C_CLASSES + lab); // L1/L2 hit
            float p  = ex2(fmaf(xl, L2E, -m2)) * inv;
            int   b  = __float2int_ru(p * (float)NB) - 1;
            b = max(0, min(NB - 1, b));
            atomicAdd(&g_acc[lab * NB + b], 1.0f);
        }

        // ---- rare path: any p > 1/NB possible iff s < NB (since max e == 1) ----
        if (s < (float)NB) {
            if (lane == 0) g_rareflag = 1;
            #pragma unroll
            for (int j = 0; j < JMAX; j++) {
                int idx = j * 32 + lane;
                if (idx < NF4) {
                    #pragma unroll
                    for (int k = 0; k < 4; k++) {
                        float p = e[j * 4 + k] * inv;
                        float t = p * (float)NB;
                        if (t > 1.0f) {
                            int b = __float2int_ru(t) - 1;
                            if (b > NB - 1) b = NB - 1;
                            int c = (idx * 4 + k);
                            atomicAdd(&g_cnthi[c * NB + b], 1.0f);
                            atomicAdd(&g_confhi[c * NB + b], p);
                        }
                    }
                }
            }
        }

        #pragma unroll
        for (int j = 0; j < JMAX; j++) v[j] = nv[j];
        lab = nlab;
        r = rn;
    }

    // ---- flush register accumulators: smem reduce, then global REDG ----
    #pragma unroll
    for (int j = 0; j < JMAX; j++) {
        int idx = j * 32 + lane;
        if (idx < NF4) {
            #pragma unroll
            for (int k = 0; k < 4; k++)
                atomicAdd(&shc[idx * 4 + k], acc[j * 4 + k]);
        }
    }
    __syncthreads();
    for (int i = threadIdx.x; i < C_CLASSES; i += TPB)
        atomicAdd(&g_colsum[i], shc[i]);

    // ================= last-block finalize (ticket handshake) =================
    __shared__ bool s_last;
    __syncthreads();
    if (threadIdx.x == 0) {
        __threadfence();                              // publish all our writes
        unsigned t = atomicInc(&g_ticket, GRID - 1);  // wraps to 0: self-reset
        s_last = (t == GRID - 1);
    }
    __syncthreads();
    if (!s_last) return;

    const bool rare = (g_rareflag != 0);
    const float invn = 1.0f / (float)n;
    float sce = 0.0f;

    if (!rare) {
        // Exact fast path: every element (incl. label class) is in bin 0.
        // cnt0 = n, prop = 1 -> contribution |colsum - acc0| / n. Reset as we go.
        for (int c = threadIdx.x; c < C_CLASSES; c += TPB) {
            float cs = g_colsum[c];
            float a0 = g_acc[c * NB];
            sce += fabsf(cs - a0) * invn;
            g_colsum[c]  = 0.0f;
            g_acc[c * NB] = 0.0f;
        }
    } else {
        for (int c = threadIdx.x; c < C_CLASSES; c += TPB) {
            float hiCnt = 0.0f, hiConf = 0.0f;
            #pragma unroll
            for (int b = 1; b < NB; b++) {
                hiCnt  += g_cnthi[c * NB + b];
                hiConf += g_confhi[c * NB + b];
            }
            {   // bin 0 (implicit: totals minus rare bins)
                float cnt0  = (float)n - hiCnt;
                float conf0 = g_colsum[c] - hiConf;
                float acc0  = g_acc[c * NB + 0];
                if (cnt0 > 0.0f)
                    sce += fabsf(conf0 - acc0) / cnt0 * (cnt0 * invn);
            }
            #pragma unroll
            for (int b = 1; b < NB; b++) {
                float cb = g_cnthi[c * NB + b];
                if (cb > 0.0f)
                    sce += fabsf(g_confhi[c * NB + b] - g_acc[c * NB + b]) / cb
                           * (cb * invn);
            }
            // full reset for this class
            g_colsum[c] = 0.0f;
            #pragma unroll
            for (int b = 0; b < NB; b++) {
                g_cnthi[c * NB + b]  = 0.0f;
                g_confhi[c * NB + b] = 0.0f;
                g_acc[c * NB + b]    = 0.0f;
            }
        }
        if (threadIdx.x == 0) g_rareflag = 0;
    }

    // block reduction of sce over 256 threads (8 warps)
    __shared__ float sh[8];
    #pragma unroll
    for (int o = 16; o; o >>= 1) sce += __shfl_xor_sync(0xFFFFFFFFu, sce, o);
    if (lane == 0) sh[threadIdx.x >> 5] = sce;
    __syncthreads();
    if (threadIdx.x < 32) {
        float vv = (lane < 8) ? sh[lane] : 0.0f;
        #pragma unroll
        for (int o = 4; o; o >>= 1) vv += __shfl_xor_sync(0xFFFFFFFFu, vv, o);
        if (lane == 0) out[0] = vv / (float)C_CLASSES;
    }
}

extern "C" void kernel_launch(void* const* d_in, const int* in_sizes, int n_in,
                              void* d_out, int out_size) {
    const float* logits = (const float*)d_in[0];
    const int*   labels = (const int*)d_in[1];
    const int n = in_sizes[1];              // number of rows = label count

    ece_main_kernel<<<GRID, TPB>>>(logits, labels, n, (float*)d_out);
}

// round 5
// speedup vs baseline: 1.0220x; 1.0220x over previous
#include <cuda_runtime.h>
#include <math_constants.h>
#include <stdint.h>

#define C_CLASSES 1000
#define NB 15
#define NSEG (C_CLASSES * NB)
#define NF4 250            // float4 chunks per row
#define JMAX 8             // ceil(NF4/32)
#define GRID 296
#define TPB 256

// Scratch accumulators. Zero at module load; the final kernel restores
// everything it consumed to zero, so each launch / graph replay starts clean.
__device__ float g_colsum[C_CLASSES];   // per-class sum of probs (all bins)
__device__ float g_cnthi[NSEG];         // counts for bins >= 1 (bin0 implicit)
__device__ float g_confhi[NSEG];        // conf sums for bins >= 1
__device__ float g_acc[NSEG];           // label-match counts, all bins
__device__ int g_rareflag;              // any row had s < NB (some p may exceed 1/NB)

__device__ __forceinline__ float ex2(float x) {
    float y;
    asm("ex2.approx.ftz.f32 %0, %1;" : "=f"(y) : "f"(x));
    return y;
}

__global__ __launch_bounds__(TPB, 2)
void ece_main_kernel(const float* __restrict__ logits,
                     const int*   __restrict__ labels,
                     int n) {
    const int lane = threadIdx.x & 31;
    const int gw   = blockIdx.x * (TPB >> 5) + (threadIdx.x >> 5); // global warp id
    const int W    = GRID * (TPB >> 5);                            // total warps

    __shared__ float shc[C_CLASSES];
    for (int i = threadIdx.x; i < C_CLASSES; i += TPB) shc[i] = 0.0f;
    __syncthreads();

    // Per-thread column-sum accumulators: class 4*(j*32+lane)+k -> acc[j*4+k]
    float acc[32];
    #pragma unroll
    for (int i = 0; i < 32; i++) acc[i] = 0.0f;

    const float L2E = 1.4426950408889634f;
    const float NEG = -CUDART_INF_F;

    int r = gw;

    // ---- prologue: load first row ----
    float4 v[JMAX];
    int lab = 0;
    if (r < n) {
        const float* row = logits + (size_t)r * C_CLASSES;
        #pragma unroll
        for (int j = 0; j < JMAX; j++) {
            int idx = j * 32 + lane;
            v[j] = (idx < NF4) ? *(const float4*)(row + idx * 4)
                               : make_float4(NEG, NEG, NEG, NEG);
        }
        lab = __ldg(labels + r);
    }

    while (r < n) {
        const int rn = r + W;

        // ---- prefetch next row: overlaps this row's entire compute chain ----
        float4 nv[JMAX];
        int nlab = 0;
        if (rn < n) {
            const float* nrow = logits + (size_t)rn * C_CLASSES;
            #pragma unroll
            for (int j = 0; j < JMAX; j++) {
                int idx = j * 32 + lane;
                nv[j] = (idx < NF4) ? *(const float4*)(nrow + idx * 4)
                                    : make_float4(NEG, NEG, NEG, NEG);
            }
            nlab = __ldg(labels + rn);
        }

        // ---- row max: local tree + warp butterfly ----
        float m = NEG;
        #pragma unroll
        for (int j = 0; j < JMAX; j++) {
            float a = fmaxf(v[j].x, v[j].y);
            float b = fmaxf(v[j].z, v[j].w);
            m = fmaxf(m, fmaxf(a, b));
        }
        #pragma unroll
        for (int o = 16; o; o >>= 1)
            m = fmaxf(m, __shfl_xor_sync(0xFFFFFFFFu, m, o));

        // ---- exp via single MUFU per element: e = 2^(x*L2E - m*L2E) ----
        const float m2 = m * L2E;
        float e[32];
        #pragma unroll
        for (int j = 0; j < JMAX; j++) {
            e[j * 4 + 0] = ex2(fmaf(v[j].x, L2E, -m2));
            e[j * 4 + 1] = ex2(fmaf(v[j].y, L2E, -m2));
            e[j * 4 + 2] = ex2(fmaf(v[j].z, L2E, -m2));
            e[j * 4 + 3] = ex2(fmaf(v[j].w, L2E, -m2));
        }

        // ---- row sum: local tree + warp butterfly ----
        float s = 0.0f;
        #pragma unroll
        for (int j = 0; j < JMAX; j++)
            s += (e[j * 4 + 0] + e[j * 4 + 1]) + (e[j * 4 + 2] + e[j * 4 + 3]);
        #pragma unroll
        for (int o = 16; o; o >>= 1)
            s += __shfl_xor_sync(0xFFFFFFFFu, s, o);

        const float inv = __fdividef(1.0f, s);

        // ---- accumulate per-class prob sums in registers (32 FFMA) ----
        #pragma unroll
        for (int i = 0; i < 32; i++)
            acc[i] = fmaf(e[i], inv, acc[i]);

        // ---- label bin: one atomic per row, handled by the owning lane ----
        if (((lab >> 2) & 31) == lane) {
            float xl = __ldg(logits + (size_t)r * C_CLASSES + lab); // L1/L2 hit
            float p  = ex2(fmaf(xl, L2E, -m2)) * inv;
            int   b  = __float2int_ru(p * (float)NB) - 1;
            b = max(0, min(NB - 1, b));
            atomicAdd(&g_acc[lab * NB + b], 1.0f);
        }

        // ---- rare path: any p > 1/NB possible iff s < NB (since max e == 1) ----
        if (s < (float)NB) {
            if (lane == 0) g_rareflag = 1;
            #pragma unroll
            for (int j = 0; j < JMAX; j++) {
                int idx = j * 32 + lane;
                if (idx < NF4) {
                    #pragma unroll
                    for (int k = 0; k < 4; k++) {
                        float p = e[j * 4 + k] * inv;
                        float t = p * (float)NB;
                        if (t > 1.0f) {
                            int b = __float2int_ru(t) - 1;
                            if (b > NB - 1) b = NB - 1;
                            int c = (idx * 4 + k);
                            atomicAdd(&g_cnthi[c * NB + b], 1.0f);
                            atomicAdd(&g_confhi[c * NB + b], p);
                        }
                    }
                }
            }
        }

        #pragma unroll
        for (int j = 0; j < JMAX; j++) v[j] = nv[j];
        lab = nlab;
        r = rn;
    }

    // ---- flush register accumulators: smem reduce, then global REDG ----
    #pragma unroll
    for (int j = 0; j < JMAX; j++) {
        int idx = j * 32 + lane;
        if (idx < NF4) {
            #pragma unroll
            for (int k = 0; k < 4; k++)
                atomicAdd(&shc[idx * 4 + k], acc[j * 4 + k]);
        }
    }
    __syncthreads();
    for (int i = threadIdx.x; i < C_CLASSES; i += TPB)
        atomicAdd(&g_colsum[i], shc[i]);
}

__global__ __launch_bounds__(1024)
void ece_final_kernel(float* __restrict__ out, int n) {
    const int c    = threadIdx.x;
    const int lane = c & 31;
    const int warp = c >> 5;

    const bool rare = (g_rareflag != 0);
    const float invn = 1.0f / (float)n;
    float sce = 0.0f;

    if (!rare) {
        // Exact fast path: every element (incl. each row's label class) is in
        // bin 0, so cnt0 = n, prop = 1, contribution = |colsum - acc0| / n.
        // Only g_colsum and the bin-0 stripe of g_acc were ever written.
        if (c < C_CLASSES) {
            float cs = g_colsum[c];
            float a0 = g_acc[c * NB];
            sce = fabsf(cs - a0) * invn;
            g_colsum[c]   = 0.0f;
            g_acc[c * NB] = 0.0f;
        }
    } else {
        if (c < C_CLASSES) {
            float hiCnt = 0.0f, hiConf = 0.0f;
            #pragma unroll
            for (int b = 1; b < NB; b++) {
                hiCnt  += g_cnthi[c * NB + b];
                hiConf += g_confhi[c * NB + b];
            }
            {   // bin 0 (implicit: totals minus rare bins)
                float cnt0  = (float)n - hiCnt;
                float conf0 = g_colsum[c] - hiConf;
                float acc0  = g_acc[c * NB + 0];
                if (cnt0 > 0.0f)
                    sce += fabsf(conf0 - acc0) / cnt0 * (cnt0 * invn);
            }
            #pragma unroll
            for (int b = 1; b < NB; b++) {
                float cb = g_cnthi[c * NB + b];
                if (cb > 0.0f)
                    sce += fabsf(g_confhi[c * NB + b] - g_acc[c * NB + b]) / cb
                           * (cb * invn);
            }
            // full reset for this class
            g_colsum[c] = 0.0f;
            #pragma unroll
            for (int b = 0; b < NB; b++) {
                g_cnthi[c * NB + b]  = 0.0f;
                g_confhi[c * NB + b] = 0.0f;
                g_acc[c * NB + b]    = 0.0f;
            }
        }
        if (c == 0) g_rareflag = 0;
    }

    __shared__ float sh[32];
    #pragma unroll
    for (int o = 16; o; o >>= 1) sce += __shfl_xor_sync(0xFFFFFFFFu, sce, o);
    if (lane == 0) sh[warp] = sce;
    __syncthreads();
    if (warp == 0) {
        float v = sh[lane];
        #pragma unroll
        for (int o = 16; o; o >>= 1) v += __shfl_xor_sync(0xFFFFFFFFu, v, o);
        if (lane == 0) out[0] = v / (float)C_CLASSES;
    }
}

extern "C" void kernel_launch(void* const* d_in, const int* in_sizes, int n_in,
                              void* d_out, int out_size) {
    const float* logits = (const float*)d_in[0];
    const int*   labels = (const int*)d_in[1];
    const int n = in_sizes[1];              // number of rows = label count

    ece_main_kernel<<<GRID, TPB>>>(logits, labels, n);
    ece_final_kernel<<<1, 1024>>>((float*)d_out, n);
}

// round 6
// speedup vs baseline: 1.3130x; 1.2847x over previous
#include <cuda_runtime.h>
#include <math_constants.h>
#include <stdint.h>

#define C_CLASSES 1000
#define NB 15
#define NSEG (C_CLASSES * NB)
#define NF4 250            // float4 chunks per row
#define JMAX 8             // ceil(NF4/32)
#define GRID 296
#define TPB 256

// Scratch accumulators. Zero at module load; the final kernel restores
// everything it consumed to zero, so each launch / graph replay starts clean.
__device__ float g_colsum[C_CLASSES];   // per-class sum of probs (all bins)
__device__ float g_cnthi[NSEG];         // counts for bins >= 1 (bin0 implicit)
__device__ float g_confhi[NSEG];        // conf sums for bins >= 1
__device__ float g_acc[NSEG];           // label-match counts, all bins

__device__ __forceinline__ float ex2(float x) {
    float y;
    asm("ex2.approx.ftz.f32 %0, %1;" : "=f"(y) : "f"(x));
    return y;
}

__global__ __launch_bounds__(TPB, 2)
void ece_main_kernel(const float* __restrict__ logits,
                     const int*   __restrict__ labels,
                     int n, float* __restrict__ out) {
    // zero the output accumulator (stream-ordered before the final kernel)
    if (blockIdx.x == 0 && threadIdx.x == 0) out[0] = 0.0f;

    const int lane = threadIdx.x & 31;
    const int gw   = blockIdx.x * (TPB >> 5) + (threadIdx.x >> 5); // global warp id
    const int W    = GRID * (TPB >> 5);                            // total warps

    __shared__ float shc[C_CLASSES];
    for (int i = threadIdx.x; i < C_CLASSES; i += TPB) shc[i] = 0.0f;
    __syncthreads();

    // Per-thread column-sum accumulators: class 4*(j*32+lane)+k -> acc[j*4+k]
    float acc[32];
    #pragma unroll
    for (int i = 0; i < 32; i++) acc[i] = 0.0f;

    const float L2E = 1.4426950408889634f;
    const float NEG = -CUDART_INF_F;

    int r = gw;

    // ---- prologue: load first row ----
    float4 v[JMAX];
    int lab = 0;
    if (r < n) {
        const float* row = logits + (size_t)r * C_CLASSES;
        #pragma unroll
        for (int j = 0; j < JMAX; j++) {
            int idx = j * 32 + lane;
            v[j] = (idx < NF4) ? *(const float4*)(row + idx * 4)
                               : make_float4(NEG, NEG, NEG, NEG);
        }
        lab = __ldg(labels + r);
    }

    while (r < n) {
        const int rn = r + W;

        // ---- prefetch next row: overlaps this row's entire compute chain ----
        float4 nv[JMAX];
        int nlab = 0;
        if (rn < n) {
            const float* nrow = logits + (size_t)rn * C_CLASSES;
            #pragma unroll
            for (int j = 0; j < JMAX; j++) {
                int idx = j * 32 + lane;
                nv[j] = (idx < NF4) ? *(const float4*)(nrow + idx * 4)
                                    : make_float4(NEG, NEG, NEG, NEG);
            }
            nlab = __ldg(labels + rn);
        }

        // ---- row max: local tree + warp butterfly ----
        float m = NEG;
        #pragma unroll
        for (int j = 0; j < JMAX; j++) {
            float a = fmaxf(v[j].x, v[j].y);
            float b = fmaxf(v[j].z, v[j].w);
            m = fmaxf(m, fmaxf(a, b));
        }
        #pragma unroll
        for (int o = 16; o; o >>= 1)
            m = fmaxf(m, __shfl_xor_sync(0xFFFFFFFFu, m, o));

        // ---- exp via single MUFU per element: e = 2^(x*L2E - m*L2E) ----
        const float m2 = m * L2E;
        float e[32];
        #pragma unroll
        for (int j = 0; j < JMAX; j++) {
            e[j * 4 + 0] = ex2(fmaf(v[j].x, L2E, -m2));
            e[j * 4 + 1] = ex2(fmaf(v[j].y, L2E, -m2));
            e[j * 4 + 2] = ex2(fmaf(v[j].z, L2E, -m2));
            e[j * 4 + 3] = ex2(fmaf(v[j].w, L2E, -m2));
        }

        // ---- row sum: local tree + warp butterfly ----
        float s = 0.0f;
        #pragma unroll
        for (int j = 0; j < JMAX; j++)
            s += (e[j * 4 + 0] + e[j * 4 + 1]) + (e[j * 4 + 2] + e[j * 4 + 3]);
        #pragma unroll
        for (int o = 16; o; o >>= 1)
            s += __shfl_xor_sync(0xFFFFFFFFu, s, o);

        const float inv = __fdividef(1.0f, s);

        // ---- accumulate per-class prob sums in registers (32 FFMA) ----
        #pragma unroll
        for (int i = 0; i < 32; i++)
            acc[i] = fmaf(e[i], inv, acc[i]);

        // ---- label bin: one atomic per row, handled by the owning lane ----
        if (((lab >> 2) & 31) == lane) {
            float xl = __ldg(logits + (size_t)r * C_CLASSES + lab); // L1/L2 hit
            float p  = ex2(fmaf(xl, L2E, -m2)) * inv;
            int   b  = __float2int_ru(p * (float)NB) - 1;
            b = max(0, min(NB - 1, b));
            atomicAdd(&g_acc[lab * NB + b], 1.0f);
        }

        // ---- rare path: any p > 1/NB possible iff s < NB (since max e == 1) ----
        if (s < (float)NB) {
            #pragma unroll
            for (int j = 0; j < JMAX; j++) {
                int idx = j * 32 + lane;
                if (idx < NF4) {
                    #pragma unroll
                    for (int k = 0; k < 4; k++) {
                        float p = e[j * 4 + k] * inv;
                        float t = p * (float)NB;
                        if (t > 1.0f) {
                            int b = __float2int_ru(t) - 1;
                            if (b > NB - 1) b = NB - 1;
                            int c = (idx * 4 + k);
                            atomicAdd(&g_cnthi[c * NB + b], 1.0f);
                            atomicAdd(&g_confhi[c * NB + b], p);
                        }
                    }
                }
            }
        }

        #pragma unroll
        for (int j = 0; j < JMAX; j++) v[j] = nv[j];
        lab = nlab;
        r = rn;
    }

    // ---- flush register accumulators: smem reduce, then global REDG ----
    #pragma unroll
    for (int j = 0; j < JMAX; j++) {
        int idx = j * 32 + lane;
        if (idx < NF4) {
            #pragma unroll
            for (int k = 0; k < 4; k++)
                atomicAdd(&shc[idx * 4 + k], acc[j * 4 + k]);
        }
    }
    __syncthreads();
    for (int i = threadIdx.x; i < C_CLASSES; i += TPB)
        atomicAdd(&g_colsum[i], shc[i]);
}

// One thread per class; 8 blocks x 128 threads = 1024 threads cover 1000
// classes with coalesced 60B-stripe reads. Per-bin terms are separable:
//   b>=1, cnt>0:  |confhi - acc_b| / n        (count cancels)
//   b==0:         |colsum - hiConf - acc0| / n (cnt0 = n - hiCnt > 0)
// Zeroing is conditional: only entries that were actually written get stores.
__global__ __launch_bounds__(128)
void ece_final_kernel(float* __restrict__ out, int n) {
    const int c    = blockIdx.x * 128 + threadIdx.x;
    const int lane = threadIdx.x & 31;

    float sce = 0.0f;
    if (c < C_CLASSES) {
        const float invn = 1.0f / (float)n;
        const int base = c * NB;

        float cnt[NB], conf[NB], ac[NB];
        #pragma unroll
        for (int b = 0; b < NB; b++) {
            cnt[b]  = g_cnthi[base + b];
            conf[b] = g_confhi[base + b];
            ac[b]   = g_acc[base + b];
        }
        float colsum = g_colsum[c];

        float hiCnt = 0.0f, hiConf = 0.0f;
        #pragma unroll
        for (int b = 1; b < NB; b++) { hiCnt += cnt[b]; hiConf += conf[b]; }

        // bin 0 (implicit)
        float cnt0 = (float)n - hiCnt;
        if (cnt0 > 0.0f)
            sce += fabsf(colsum - hiConf - ac[0]) * invn;

        // bins >= 1
        #pragma unroll
        for (int b = 1; b < NB; b++)
            if (cnt[b] > 0.0f)
                sce += fabsf(conf[b] - ac[b]) * invn;

        // conditional reset (acc[b]!=0 for b>=1 implies cnt[b]!=0)
        g_colsum[c] = 0.0f;
        if (ac[0] != 0.0f) g_acc[base] = 0.0f;
        #pragma unroll
        for (int b = 1; b < NB; b++) {
            if (cnt[b] != 0.0f) {
                g_cnthi[base + b]  = 0.0f;
                g_confhi[base + b] = 0.0f;
                g_acc[base + b]    = 0.0f;
            }
        }

        sce *= (1.0f / (float)C_CLASSES);
    }

    // block-level reduction, then one atomic per block
    __shared__ float sh[4];
    #pragma unroll
    for (int o = 16; o; o >>= 1) sce += __shfl_xor_sync(0xFFFFFFFFu, sce, o);
    if (lane == 0) sh[threadIdx.x >> 5] = sce;
    __syncthreads();
    if (threadIdx.x == 0) {
        float v = sh[0] + sh[1] + sh[2] + sh[3];
        atomicAdd(out, v);
    }
}

extern "C" void kernel_launch(void* const* d_in, const int* in_sizes, int n_in,
                              void* d_out, int out_size) {
    const float* logits = (const float*)d_in[0];
    const int*   labels = (const int*)d_in[1];
    const int n = in_sizes[1];              // number of rows = label count

    ece_main_kernel<<<GRID, TPB>>>(logits, labels, n, (float*)d_out);
    ece_final_kernel<<<8, 128>>>((float*)d_out, n);
}